// round 16
// baseline (speedup 1.0000x reference)
#include <cuda_runtime.h>
#include <cuda_fp16.h>

#define NN   50000
#define NE   800000
#define NG   512
#define CH   64
#define CAP  128               // bucket capacity per dst node
#define FULL 0xffffffffu
#define NTILE (NN / 16)        // 3125 gemm tiles
#define GEMM_BLKS ((NTILE * 32 + 255) / 256)   // 391
#define SCAT_BLKS ((NE / 4 + 255) / 256)       // 782

// ---------------- scratch (device globals; no allocations allowed) ----------
__device__ float2 g_h[NN * 32];    // per-layer h = X @ W  (fp32, row = 32 float2)
__device__ float2 g_out[NN * 32];  // per-layer aggregated + elu output (fp32)
__device__ float g_as[NN];
__device__ float g_ad[NN];
__device__ int   g_deg[NN];        // edge counters; zeroed by k_div (state restore)
__device__ int   g_bkt[NN * CAP];  // src node per dst bucket slot (25.6 MB)
__device__ float g_pool[NG * CH];  // zeroed by scatter-path spare threads
__device__ float g_cnt[NG];

__device__ __forceinline__ int clampi(long long v, int lim) {
    if (v < 0) v = 0;
    if (v >= lim) v = lim - 1;
    return (int)v;
}

__device__ __forceinline__ int ld_idx(const void* __restrict__ p, long long i, int is32, int lim) {
    long long v = is32 ? (long long)((const int*)p)[i] : ((const long long*)p)[i];
    return clampi(v, lim);
}

// ---- packed f32x2 helpers (Blackwell FFMA2; PTX-only per SASS_QUICKREF) ----
__device__ __forceinline__ unsigned long long pk2(float v) {
    unsigned long long r;
    asm("mov.b64 %0, {%1, %1};" : "=l"(r) : "f"(v));
    return r;
}
__device__ __forceinline__ void fma2(unsigned long long& d,
                                     unsigned long long a, unsigned long long b) {
    asm("fma.rn.f32x2 %0, %1, %2, %0;" : "+l"(d) : "l"(a), "l"(b));
}
__device__ __forceinline__ void upk(unsigned long long v, float& lo, float& hi) {
    asm("mov.b64 {%0, %1}, %2;" : "=f"(lo), "=f"(hi) : "l"(v));
}

// per-block dtype detection (first 64 values of ei must be < NN if int64)
__device__ __forceinline__ int block_detect(const void* __restrict__ ei) {
    __shared__ int s_is32;
    if (threadIdx.x < 32) {
        const long long* p = (const long long*)ei;
        long long v0 = p[threadIdx.x];
        long long v1 = p[threadIdx.x + 32];
        int bad = (v0 < 0 || v0 >= NN || v1 < 0 || v1 >= NN);
        unsigned any = __ballot_sync(FULL, bad);
        if (threadIdx.x == 0) s_is32 = (any != 0u) ? 1 : 0;
    }
    __syncthreads();
    return s_is32;
}

// ---------------- scatter body (4 edges/thread) into buckets ----------------
__device__ __forceinline__ void scatter_body(const void* __restrict__ ei, int bid) {
    int is32 = block_detect(ei);
    int t = bid * 256 + threadIdx.x;
    if (t < NG * CH) g_pool[t] = 0.0f;
    if (t < NG) g_cnt[t] = 0.0f;
    if (t >= NE / 4) return;
    int d0, d1, d2, d3, s0, s1, s2, s3;
    if (is32) {
        int4 dd = ((const int4*)ei)[NE / 4 + t];
        int4 ss = ((const int4*)ei)[t];
        d0 = clampi(dd.x, NN); d1 = clampi(dd.y, NN);
        d2 = clampi(dd.z, NN); d3 = clampi(dd.w, NN);
        s0 = clampi(ss.x, NN); s1 = clampi(ss.y, NN);
        s2 = clampi(ss.z, NN); s3 = clampi(ss.w, NN);
    } else {
        longlong2 da = ((const longlong2*)ei)[NE / 2 + 2 * t];
        longlong2 db = ((const longlong2*)ei)[NE / 2 + 2 * t + 1];
        longlong2 sa = ((const longlong2*)ei)[2 * t];
        longlong2 sb = ((const longlong2*)ei)[2 * t + 1];
        d0 = clampi(da.x, NN); d1 = clampi(da.y, NN);
        d2 = clampi(db.x, NN); d3 = clampi(db.y, NN);
        s0 = clampi(sa.x, NN); s1 = clampi(sa.y, NN);
        s2 = clampi(sb.x, NN); s3 = clampi(sb.y, NN);
    }
    int r0 = atomicAdd(&g_deg[d0], 1);
    int r1 = atomicAdd(&g_deg[d1], 1);
    int r2 = atomicAdd(&g_deg[d2], 1);
    int r3 = atomicAdd(&g_deg[d3], 1);
    if (r0 < CAP) g_bkt[d0 * CAP + r0] = s0;
    if (r1 < CAP) g_bkt[d1 * CAP + r1] = s1;
    if (r2 < CAP) g_bkt[d2 * CAP + r2] = s2;
    if (r3 < CAP) g_bkt[d3 * CAP + r3] = s3;
}

// ---------------- gemm body: h = X @ W via tensor cores (mma.m16n8k16) ------
__device__ __forceinline__ void gemm_body(const float2* __restrict__ Xp,
                                          const float* __restrict__ W,
                                          const float* __restrict__ a_src,
                                          const float* __restrict__ a_dst,
                                          int bid,
                                          __half* sWt, float2* s_as, float2* s_ad) {
    const int tid = threadIdx.x;
    for (int idx = tid; idx < 64 * 64; idx += 256) {
        int k = idx >> 6, n = idx & 63;
        sWt[n * 72 + k] = __float2half(W[idx]);
    }
    if (tid < 32) {
        s_as[tid] = ((const float2*)a_src)[tid];
        s_ad[tid] = ((const float2*)a_dst)[tid];
    }
    __syncthreads();

    const int gw = (bid * 256 + tid) >> 5;
    if (gw >= NTILE) return;
    const int i0 = gw * 16;
    const int lane = tid & 31;
    const int q  = lane & 3;     // quad position
    const int rr = lane >> 2;    // fragment row 0..7

    // A fragments: 16 independent LDG.64 + in-register fp16 convert
    unsigned a[4][4];
    {
        const float2* xr0 = &Xp[(i0 + rr) * 32];
        const float2* xr1 = &Xp[(i0 + rr + 8) * 32];
        #pragma unroll
        for (int kt = 0; kt < 4; kt++) {
            float2 f0 = xr0[kt * 8 + q];
            float2 f1 = xr1[kt * 8 + q];
            float2 f2 = xr0[kt * 8 + 4 + q];
            float2 f3 = xr1[kt * 8 + 4 + q];
            __half2 h0 = __floats2half2_rn(f0.x, f0.y);
            __half2 h1 = __floats2half2_rn(f1.x, f1.y);
            __half2 h2 = __floats2half2_rn(f2.x, f2.y);
            __half2 h3 = __floats2half2_rn(f3.x, f3.y);
            a[kt][0] = *(unsigned*)&h0;
            a[kt][1] = *(unsigned*)&h1;
            a[kt][2] = *(unsigned*)&h2;
            a[kt][3] = *(unsigned*)&h3;
        }
    }

    float prlo = 0.f, prhi = 0.f, pdlo = 0.f, pdhi = 0.f;

    #pragma unroll
    for (int nt = 0; nt < 8; nt++) {
        float c0 = 0.f, c1 = 0.f, c2 = 0.f, c3 = 0.f;
        const __half* wb = &sWt[(nt * 8 + rr) * 72];
        #pragma unroll
        for (int kt = 0; kt < 4; kt++) {
            unsigned b0 = *(const unsigned*)(wb + kt * 16 + q * 2);
            unsigned b1 = *(const unsigned*)(wb + kt * 16 + 8 + q * 2);
            asm volatile(
                "mma.sync.aligned.m16n8k16.row.col.f32.f16.f16.f32 "
                "{%0,%1,%2,%3}, {%4,%5,%6,%7}, {%8,%9}, {%0,%1,%2,%3};"
                : "+f"(c0), "+f"(c1), "+f"(c2), "+f"(c3)
                : "r"(a[kt][0]), "r"(a[kt][1]), "r"(a[kt][2]), "r"(a[kt][3]),
                  "r"(b0), "r"(b1));
        }
        int cp = nt * 4 + q;   // colpair index 0..31
        g_h[(i0 + rr) * 32 + cp]     = make_float2(c0, c1);
        g_h[(i0 + rr + 8) * 32 + cp] = make_float2(c2, c3);
        float2 av = s_as[cp], dv = s_ad[cp];
        prlo += c0 * av.x + c1 * av.y;
        prhi += c2 * av.x + c3 * av.y;
        pdlo += c0 * dv.x + c1 * dv.y;
        pdhi += c2 * dv.x + c3 * dv.y;
    }

    prlo += __shfl_xor_sync(FULL, prlo, 1); prlo += __shfl_xor_sync(FULL, prlo, 2);
    prhi += __shfl_xor_sync(FULL, prhi, 1); prhi += __shfl_xor_sync(FULL, prhi, 2);
    pdlo += __shfl_xor_sync(FULL, pdlo, 1); pdlo += __shfl_xor_sync(FULL, pdlo, 2);
    pdhi += __shfl_xor_sync(FULL, pdhi, 1); pdhi += __shfl_xor_sync(FULL, pdhi, 2);
    if (q == 0) {
        g_as[i0 + rr]     = prlo;  g_ad[i0 + rr]     = pdlo;
        g_as[i0 + rr + 8] = prhi;  g_ad[i0 + rr + 8] = pdhi;
    }
}

// ---------------- fused front: gemm1 (blocks<391) + scatter (rest) ----------
__global__ void k_front(const float2* __restrict__ X2,
                        const float* __restrict__ W,
                        const float* __restrict__ a_src,
                        const float* __restrict__ a_dst,
                        const void* __restrict__ ei) {
    __shared__ __half sWt[64 * 72];
    __shared__ float2 s_as[32], s_ad[32];
    if (blockIdx.x < GEMM_BLKS) {
        gemm_body(X2, W, a_src, a_dst, blockIdx.x, sWt, s_as, s_ad);
    } else {
        scatter_body(ei, blockIdx.x - GEMM_BLKS);
    }
}

// ---------------- standalone gemm (layer 2, input = g_out) ------------------
__global__ void k_gemm2(const float* __restrict__ W,
                        const float* __restrict__ a_src,
                        const float* __restrict__ a_dst) {
    __shared__ __half sWt[64 * 72];
    __shared__ float2 s_as[32], s_ad[32];
    gemm_body((const float2*)g_out, W, a_src, a_dst, blockIdx.x, sWt, s_as, s_ad);
}

// ---------------- warp-per-dst: softmax + quad-split fp32 aggregation -------
// lane = eg (edge subgroup, lane>>3) x cl (channel lane, lane&7).
// Each lane loads 8 fp32 channels of one edge via 2x LDG.128; f32x2 FMAs.
__global__ void k_agg(const float* __restrict__ bias) {
    const int w = (blockIdx.x * blockDim.x + threadIdx.x) >> 5;
    const int lane = threadIdx.x & 31;
    if (w >= NN) return;
    const int eg = lane >> 3;    // edge subgroup 0..3
    const int cl = lane & 7;     // channel lane (8 channels each)

    const int base = w * CAP;

    // all independent loads issued up front (buckets always legal; stale slots
    // hold valid clamped node ids whose weights end up exactly 0)
    int sn_r[4];
    #pragma unroll
    for (int c = 0; c < 4; c++) sn_r[c] = g_bkt[base + c * 32 + lane];
    const int deg = min(g_deg[w], CAP);   // stored edges (self loop implicit)
    const float adi = g_ad[w];

    float l_self = g_as[w] + adi;
    l_self = (l_self >= 0.f) ? l_self : 0.2f * l_self;

    float l_r[4];
    #pragma unroll
    for (int c = 0; c < 4; c++) l_r[c] = g_as[sn_r[c]];

    const int nch = (deg + 31) >> 5;
    float m = -1e30f, s = 0.f;
    #pragma unroll
    for (int c = 0; c < 4; c++) {
        int e = c * 32 + lane;
        int valid = (c < nch) && (e < deg);
        float l = -1e30f;
        if (valid) {
            l = l_r[c] + adi;
            l = (l >= 0.f) ? l : 0.2f * l;
        }
        l_r[c] = l;
        float mn = fmaxf(m, l);
        s = s * __expf(m - mn) + (valid ? __expf(l - mn) : 0.f);
        m = mn;
    }
    #pragma unroll
    for (int o = 16; o; o >>= 1) {
        float m2 = __shfl_xor_sync(FULL, m, o);
        float s2 = __shfl_xor_sync(FULL, s, o);
        float M = fmaxf(m, m2);
        s = s * __expf(m - M) + s2 * __expf(m2 - M);
        m = M;
    }
    {
        float M = fmaxf(m, l_self);
        s = s * __expf(m - M) + __expf(l_self - M);
        m = M;
    }
    const float inv = 1.0f / s;

    // ---- pass 2: quad-split gather, packed f32x2 accumulation ----
    const ulonglong2* __restrict__ H = (const ulonglong2*)g_h;
    unsigned long long a0 = 0ull, a1 = 0ull, a2 = 0ull, a3 = 0ull;  // {0,0} pairs

    #pragma unroll
    for (int c = 0; c < 4; c++) {
        if (c >= nch) break;
        int n = min(32, deg - c * 32);
        float wgt = __expf(l_r[c] - m) * inv;   // invalid lanes -> 0
        int sn = sn_r[c];
        #pragma unroll 4
        for (int j = 0; j < n; j += 8) {
            int   s1 = __shfl_sync(FULL, sn, j + eg);
            float w1 = __shfl_sync(FULL, wgt, j + eg);
            int   s2 = __shfl_sync(FULL, sn, j + 4 + eg);
            float w2 = __shfl_sync(FULL, wgt, j + 4 + eg);
            ulonglong2 v10 = H[s1 * 16 + cl * 2];
            ulonglong2 v11 = H[s1 * 16 + cl * 2 + 1];
            ulonglong2 v20 = H[s2 * 16 + cl * 2];
            ulonglong2 v21 = H[s2 * 16 + cl * 2 + 1];
            unsigned long long w1p = pk2(w1);
            unsigned long long w2p = pk2(w2);
            fma2(a0, v10.x, w1p); fma2(a1, v10.y, w1p);
            fma2(a2, v11.x, w1p); fma2(a3, v11.y, w1p);
            fma2(a0, v20.x, w2p); fma2(a1, v20.y, w2p);
            fma2(a2, v21.x, w2p); fma2(a3, v21.y, w2p);
        }
    }
    // self-loop contribution (only subgroup 0 adds it)
    {
        float ws = __expf(l_self - m) * inv;
        if (eg == 0) {
            unsigned long long wsp = pk2(ws);
            ulonglong2 v0 = H[w * 16 + cl * 2];
            ulonglong2 v1 = H[w * 16 + cl * 2 + 1];
            fma2(a0, v0.x, wsp); fma2(a1, v0.y, wsp);
            fma2(a2, v1.x, wsp); fma2(a3, v1.y, wsp);
        }
    }

    // reduce across the 4 edge subgroups
    float f[8];
    upk(a0, f[0], f[1]); upk(a1, f[2], f[3]);
    upk(a2, f[4], f[5]); upk(a3, f[6], f[7]);
    #pragma unroll
    for (int o = 8; o <= 16; o <<= 1) {
        #pragma unroll
        for (int k = 0; k < 8; k++)
            f[k] += __shfl_xor_sync(FULL, f[k], o);
    }

    if (lane < 8) {   // eg == 0: channels cl*8 .. cl*8+7
        float4 b0 = ((const float4*)bias)[cl * 2];
        float4 b1 = ((const float4*)bias)[cl * 2 + 1];
        f[0] += b0.x; f[1] += b0.y; f[2] += b0.z; f[3] += b0.w;
        f[4] += b1.x; f[5] += b1.y; f[6] += b1.z; f[7] += b1.w;
        #pragma unroll
        for (int k = 0; k < 8; k++)
            f[k] = (f[k] > 0.f) ? f[k] : expm1f(f[k]);   // elu
        ((float4*)g_out)[w * 16 + cl * 2]     = make_float4(f[0], f[1], f[2], f[3]);
        ((float4*)g_out)[w * 16 + cl * 2 + 1] = make_float4(f[4], f[5], f[6], f[7]);
    }
}

// ---------------- global mean pool (warp per 8-node run) ---------------------
#define PNODES 8
#define NGRP   ((NN + PNODES - 1) / PNODES)
__global__ void k_pool(const void* __restrict__ batch, const void* __restrict__ ei) {
    int is32 = block_detect(ei);
    const int wid = (blockIdx.x * blockDim.x + threadIdx.x) >> 5;
    const int lane = threadIdx.x & 31;
    if (wid >= NGRP) return;
    const int i0 = wid * PNODES;

    int b = 0;
    if (lane < PNODES && i0 + lane < NN) b = ld_idx(batch, i0 + lane, is32, NG);

    int gprev = __shfl_sync(FULL, b, 0);
    float ax = 0.f, ay = 0.f, cnt = 0.f;
    #pragma unroll
    for (int k = 0; k < PNODES; k++) {
        int i = i0 + k;
        if (i >= NN) break;
        int g = __shfl_sync(FULL, b, k);
        if (g != gprev) {
            atomicAdd(&g_pool[gprev * CH + 2 * lane], ax);
            atomicAdd(&g_pool[gprev * CH + 2 * lane + 1], ay);
            if (lane == 0) atomicAdd(&g_cnt[gprev], cnt);
            ax = 0.f; ay = 0.f; cnt = 0.f; gprev = g;
        }
        float2 v = g_out[i * 32 + lane];
        ax += v.x; ay += v.y; cnt += 1.f;
    }
    atomicAdd(&g_pool[gprev * CH + 2 * lane], ax);
    atomicAdd(&g_pool[gprev * CH + 2 * lane + 1], ay);
    if (lane == 0) atomicAdd(&g_cnt[gprev], cnt);
}

// ---------------- divide + writeout + zero g_deg for next launch ------------
__global__ void k_div(float* __restrict__ dout) {
    int t = blockIdx.x * blockDim.x + threadIdx.x;
    if (t < NG * CH) dout[t] = g_pool[t] * (1.0f / fmaxf(g_cnt[t >> 6], 1.0f));
    if (t < NN) g_deg[t] = 0;    // restore for next launch
}

// ---------------- entry ------------------------------------------------------
extern "C" void kernel_launch(void* const* d_in, const int* in_sizes, int n_in,
                              void* d_out, int out_size) {
    const float* x     = (const float*)d_in[0];
    const void*  ei    = d_in[1];
    const void*  batch = d_in[2];
    const float* W1    = (const float*)d_in[3];
    const float* as1   = (const float*)d_in[4];
    const float* ad1   = (const float*)d_in[5];
    const float* b1    = (const float*)d_in[6];
    const float* W2    = (const float*)d_in[7];
    const float* as2   = (const float*)d_in[8];
    const float* ad2   = (const float*)d_in[9];
    const float* b2    = (const float*)d_in[10];
    float* dout = (float*)d_out;

    // fused: gemm1 (independent of edges) + bucket scatter (independent of x)
    k_front<<<GEMM_BLKS + SCAT_BLKS, 256>>>((const float2*)x, W1, as1, ad1, ei);

    // layer 1 aggregation
    k_agg<<<(NN * 32 + 255) / 256, 256>>>(b1);

    // layer 2
    k_gemm2<<<GEMM_BLKS, 256>>>(W2, as2, ad2);
    k_agg<<<(NN * 32 + 255) / 256, 256>>>(b2);

    // pool + divide (+ g_deg restore)
    k_pool<<<(NGRP * 32 + 255) / 256, 256>>>(batch, ei);
    k_div<<<(NN + 255) / 256, 256>>>(dout);
}

// round 17
// speedup vs baseline: 1.4058x; 1.4058x over previous
#include <cuda_runtime.h>
#include <cuda_fp16.h>

#define NN   50000
#define NE   800000
#define NG   512
#define CH   64
#define CAP  128               // bucket capacity per dst node
#define FULL 0xffffffffu
#define NTILE (NN / 16)        // 3125 gemm tiles
#define GEMM_BLKS ((NTILE * 32 + 255) / 256)   // 391
#define SCAT_BLKS ((NE / 4 + 255) / 256)       // 782

// ---------------- scratch (device globals; no allocations allowed) ----------
__device__ __half2 g_h[NN * 32];   // per-layer h = X @ W  (fp16, row = 32 half2)
__device__ float2 g_out[NN * 32];  // per-layer aggregated + elu output (fp32)
__device__ float g_as[NN];
__device__ float g_ad[NN];
__device__ int   g_deg[NN];        // edge counters; zeroed by k_div (state restore)
__device__ int   g_bkt[NN * CAP];  // src node per dst bucket slot (25.6 MB)
__device__ float g_pool[NG * CH];  // zeroed by scatter-path spare threads
__device__ float g_cnt[NG];

__device__ __forceinline__ int clampi(long long v, int lim) {
    if (v < 0) v = 0;
    if (v >= lim) v = lim - 1;
    return (int)v;
}

__device__ __forceinline__ int ld_idx(const void* __restrict__ p, long long i, int is32, int lim) {
    long long v = is32 ? (long long)((const int*)p)[i] : ((const long long*)p)[i];
    return clampi(v, lim);
}

// per-block dtype detection (first 64 values of ei must be < NN if int64)
__device__ __forceinline__ int block_detect(const void* __restrict__ ei) {
    __shared__ int s_is32;
    if (threadIdx.x < 32) {
        const long long* p = (const long long*)ei;
        long long v0 = p[threadIdx.x];
        long long v1 = p[threadIdx.x + 32];
        int bad = (v0 < 0 || v0 >= NN || v1 < 0 || v1 >= NN);
        unsigned any = __ballot_sync(FULL, bad);
        if (threadIdx.x == 0) s_is32 = (any != 0u) ? 1 : 0;
    }
    __syncthreads();
    return s_is32;
}

// ---------------- scatter body (4 edges/thread) into buckets ----------------
__device__ __forceinline__ void scatter_body(const void* __restrict__ ei, int bid) {
    int is32 = block_detect(ei);
    int t = bid * 256 + threadIdx.x;
    if (t < NG * CH) g_pool[t] = 0.0f;
    if (t < NG) g_cnt[t] = 0.0f;
    if (t >= NE / 4) return;
    int d0, d1, d2, d3, s0, s1, s2, s3;
    if (is32) {
        int4 dd = ((const int4*)ei)[NE / 4 + t];
        int4 ss = ((const int4*)ei)[t];
        d0 = clampi(dd.x, NN); d1 = clampi(dd.y, NN);
        d2 = clampi(dd.z, NN); d3 = clampi(dd.w, NN);
        s0 = clampi(ss.x, NN); s1 = clampi(ss.y, NN);
        s2 = clampi(ss.z, NN); s3 = clampi(ss.w, NN);
    } else {
        longlong2 da = ((const longlong2*)ei)[NE / 2 + 2 * t];
        longlong2 db = ((const longlong2*)ei)[NE / 2 + 2 * t + 1];
        longlong2 sa = ((const longlong2*)ei)[2 * t];
        longlong2 sb = ((const longlong2*)ei)[2 * t + 1];
        d0 = clampi(da.x, NN); d1 = clampi(da.y, NN);
        d2 = clampi(db.x, NN); d3 = clampi(db.y, NN);
        s0 = clampi(sa.x, NN); s1 = clampi(sa.y, NN);
        s2 = clampi(sb.x, NN); s3 = clampi(sb.y, NN);
    }
    int r0 = atomicAdd(&g_deg[d0], 1);
    int r1 = atomicAdd(&g_deg[d1], 1);
    int r2 = atomicAdd(&g_deg[d2], 1);
    int r3 = atomicAdd(&g_deg[d3], 1);
    if (r0 < CAP) g_bkt[d0 * CAP + r0] = s0;
    if (r1 < CAP) g_bkt[d1 * CAP + r1] = s1;
    if (r2 < CAP) g_bkt[d2 * CAP + r2] = s2;
    if (r3 < CAP) g_bkt[d3 * CAP + r3] = s3;
}

// ---------------- gemm body: h = X @ W via tensor cores (mma.m16n8k16) ------
__device__ __forceinline__ void gemm_body(const float2* __restrict__ Xp,
                                          const float* __restrict__ W,
                                          const float* __restrict__ a_src,
                                          const float* __restrict__ a_dst,
                                          int bid,
                                          __half* sWt, float2* s_as, float2* s_ad) {
    const int tid = threadIdx.x;
    for (int idx = tid; idx < 64 * 64; idx += 256) {
        int k = idx >> 6, n = idx & 63;
        sWt[n * 72 + k] = __float2half(W[idx]);
    }
    if (tid < 32) {
        s_as[tid] = ((const float2*)a_src)[tid];
        s_ad[tid] = ((const float2*)a_dst)[tid];
    }
    __syncthreads();

    const int gw = (bid * 256 + tid) >> 5;
    if (gw >= NTILE) return;
    const int i0 = gw * 16;
    const int lane = tid & 31;
    const int q  = lane & 3;     // quad position
    const int rr = lane >> 2;    // fragment row 0..7

    // A fragments: 16 independent LDG.64 + in-register fp16 convert
    unsigned a[4][4];
    {
        const float2* xr0 = &Xp[(i0 + rr) * 32];
        const float2* xr1 = &Xp[(i0 + rr + 8) * 32];
        #pragma unroll
        for (int kt = 0; kt < 4; kt++) {
            float2 f0 = xr0[kt * 8 + q];
            float2 f1 = xr1[kt * 8 + q];
            float2 f2 = xr0[kt * 8 + 4 + q];
            float2 f3 = xr1[kt * 8 + 4 + q];
            __half2 h0 = __floats2half2_rn(f0.x, f0.y);
            __half2 h1 = __floats2half2_rn(f1.x, f1.y);
            __half2 h2 = __floats2half2_rn(f2.x, f2.y);
            __half2 h3 = __floats2half2_rn(f3.x, f3.y);
            a[kt][0] = *(unsigned*)&h0;
            a[kt][1] = *(unsigned*)&h1;
            a[kt][2] = *(unsigned*)&h2;
            a[kt][3] = *(unsigned*)&h3;
        }
    }

    float prlo = 0.f, prhi = 0.f, pdlo = 0.f, pdhi = 0.f;

    #pragma unroll
    for (int nt = 0; nt < 8; nt++) {
        float c0 = 0.f, c1 = 0.f, c2 = 0.f, c3 = 0.f;
        const __half* wb = &sWt[(nt * 8 + rr) * 72];
        #pragma unroll
        for (int kt = 0; kt < 4; kt++) {
            unsigned b0 = *(const unsigned*)(wb + kt * 16 + q * 2);
            unsigned b1 = *(const unsigned*)(wb + kt * 16 + 8 + q * 2);
            asm volatile(
                "mma.sync.aligned.m16n8k16.row.col.f32.f16.f16.f32 "
                "{%0,%1,%2,%3}, {%4,%5,%6,%7}, {%8,%9}, {%0,%1,%2,%3};"
                : "+f"(c0), "+f"(c1), "+f"(c2), "+f"(c3)
                : "r"(a[kt][0]), "r"(a[kt][1]), "r"(a[kt][2]), "r"(a[kt][3]),
                  "r"(b0), "r"(b1));
        }
        int cp = nt * 4 + q;   // colpair index 0..31
        g_h[(i0 + rr) * 32 + cp]     = __floats2half2_rn(c0, c1);
        g_h[(i0 + rr + 8) * 32 + cp] = __floats2half2_rn(c2, c3);
        float2 av = s_as[cp], dv = s_ad[cp];
        prlo += c0 * av.x + c1 * av.y;
        prhi += c2 * av.x + c3 * av.y;
        pdlo += c0 * dv.x + c1 * dv.y;
        pdhi += c2 * dv.x + c3 * dv.y;
    }

    prlo += __shfl_xor_sync(FULL, prlo, 1); prlo += __shfl_xor_sync(FULL, prlo, 2);
    prhi += __shfl_xor_sync(FULL, prhi, 1); prhi += __shfl_xor_sync(FULL, prhi, 2);
    pdlo += __shfl_xor_sync(FULL, pdlo, 1); pdlo += __shfl_xor_sync(FULL, pdlo, 2);
    pdhi += __shfl_xor_sync(FULL, pdhi, 1); pdhi += __shfl_xor_sync(FULL, pdhi, 2);
    if (q == 0) {
        g_as[i0 + rr]     = prlo;  g_ad[i0 + rr]     = pdlo;
        g_as[i0 + rr + 8] = prhi;  g_ad[i0 + rr + 8] = pdhi;
    }
}

// ---------------- fused front: gemm1 (blocks<391) + scatter (rest) ----------
__global__ void k_front(const float2* __restrict__ X2,
                        const float* __restrict__ W,
                        const float* __restrict__ a_src,
                        const float* __restrict__ a_dst,
                        const void* __restrict__ ei) {
    __shared__ __half sWt[64 * 72];
    __shared__ float2 s_as[32], s_ad[32];
    if (blockIdx.x < GEMM_BLKS) {
        gemm_body(X2, W, a_src, a_dst, blockIdx.x, sWt, s_as, s_ad);
    } else {
        scatter_body(ei, blockIdx.x - GEMM_BLKS);
    }
}

// ---------------- standalone gemm (layer 2, input = g_out) ------------------
__global__ void k_gemm2(const float* __restrict__ W,
                        const float* __restrict__ a_src,
                        const float* __restrict__ a_dst) {
    __shared__ __half sWt[64 * 72];
    __shared__ float2 s_as[32], s_ad[32];
    gemm_body((const float2*)g_out, W, a_src, a_dst, blockIdx.x, sWt, s_as, s_ad);
}

// ---------------- warp-per-dst: softmax + aggregation (8 edges/iter) --------
__device__ __forceinline__ void agg_window(int sn, float wgt, int n,
                                           int hw, int hl, float4& acc) {
    for (int j = 0; j < n; j += 8) {
        int   sj0 = __shfl_sync(FULL, sn, j + hw);
        float wj0 = __shfl_sync(FULL, wgt, j + hw);
        int   sj1 = __shfl_sync(FULL, sn, j + 2 + hw);
        float wj1 = __shfl_sync(FULL, wgt, j + 2 + hw);
        int   sj2 = __shfl_sync(FULL, sn, j + 4 + hw);
        float wj2 = __shfl_sync(FULL, wgt, j + 4 + hw);
        int   sj3 = __shfl_sync(FULL, sn, j + 6 + hw);
        float wj3 = __shfl_sync(FULL, wgt, j + 6 + hw);
        uint2 r0 = *reinterpret_cast<const uint2*>(&g_h[sj0 * 32 + 2 * hl]);
        uint2 r1 = *reinterpret_cast<const uint2*>(&g_h[sj1 * 32 + 2 * hl]);
        uint2 r2 = *reinterpret_cast<const uint2*>(&g_h[sj2 * 32 + 2 * hl]);
        uint2 r3 = *reinterpret_cast<const uint2*>(&g_h[sj3 * 32 + 2 * hl]);
        float2 v0a = __half22float2(*reinterpret_cast<const __half2*>(&r0.x));
        float2 v0b = __half22float2(*reinterpret_cast<const __half2*>(&r0.y));
        float2 v1a = __half22float2(*reinterpret_cast<const __half2*>(&r1.x));
        float2 v1b = __half22float2(*reinterpret_cast<const __half2*>(&r1.y));
        float2 v2a = __half22float2(*reinterpret_cast<const __half2*>(&r2.x));
        float2 v2b = __half22float2(*reinterpret_cast<const __half2*>(&r2.y));
        float2 v3a = __half22float2(*reinterpret_cast<const __half2*>(&r3.x));
        float2 v3b = __half22float2(*reinterpret_cast<const __half2*>(&r3.y));
        acc.x = fmaf(wj0, v0a.x, acc.x); acc.y = fmaf(wj0, v0a.y, acc.y);
        acc.z = fmaf(wj0, v0b.x, acc.z); acc.w = fmaf(wj0, v0b.y, acc.w);
        acc.x = fmaf(wj1, v1a.x, acc.x); acc.y = fmaf(wj1, v1a.y, acc.y);
        acc.z = fmaf(wj1, v1b.x, acc.z); acc.w = fmaf(wj1, v1b.y, acc.w);
        acc.x = fmaf(wj2, v2a.x, acc.x); acc.y = fmaf(wj2, v2a.y, acc.y);
        acc.z = fmaf(wj2, v2b.x, acc.z); acc.w = fmaf(wj2, v2b.y, acc.w);
        acc.x = fmaf(wj3, v3a.x, acc.x); acc.y = fmaf(wj3, v3a.y, acc.y);
        acc.z = fmaf(wj3, v3b.x, acc.z); acc.w = fmaf(wj3, v3b.y, acc.w);
    }
}

__global__ void k_agg(const float* __restrict__ bias) {
    const int w = (blockIdx.x * blockDim.x + threadIdx.x) >> 5;
    const int lane = threadIdx.x & 31;
    if (w >= NN) return;
    const int hw = lane >> 4;
    const int hl = lane & 15;

    const int base = w * CAP;

    // independent loads issued up front (chunk-0 bucket always legal; stale
    // slots hold valid clamped node ids whose weights end up exactly 0)
    const int sn0 = g_bkt[base + lane];
    const int deg = min(g_deg[w], CAP);   // stored edges (self loop implicit)
    const float adi = g_ad[w];
    const float as0 = g_as[sn0];

    float l_self = g_as[w] + adi;
    l_self = (l_self >= 0.f) ? l_self : 0.2f * l_self;

    float4 acc = make_float4(0.f, 0.f, 0.f, 0.f);
    float m, inv;

    if (deg <= 32) {
        // ---- fast path (98%+ of nodes): single chunk, 2-pass reg softmax ----
        const int valid = lane < deg;
        float l = as0 + adi;
        l = (l >= 0.f) ? l : 0.2f * l;
        l = valid ? l : -1e30f;
        float mx = l;
        #pragma unroll
        for (int o = 16; o; o >>= 1) mx = fmaxf(mx, __shfl_xor_sync(FULL, mx, o));
        mx = fmaxf(mx, l_self);
        float e = valid ? __expf(l - mx) : 0.f;
        float ssum = e;
        #pragma unroll
        for (int o = 16; o; o >>= 1) ssum += __shfl_xor_sync(FULL, ssum, o);
        ssum += __expf(l_self - mx);
        m = mx;
        inv = 1.0f / ssum;
        agg_window(sn0, e * inv, deg, hw, hl, acc);
    } else {
        // ---- generic path (rare): 4-chunk online softmax ----
        int sn_r[4];
        sn_r[0] = sn0;
        #pragma unroll
        for (int c = 1; c < 4; c++) sn_r[c] = g_bkt[base + c * 32 + lane];
        float l_r[4];
        l_r[0] = as0;
        #pragma unroll
        for (int c = 1; c < 4; c++) l_r[c] = g_as[sn_r[c]];

        const int nch = (deg + 31) >> 5;
        float mm = -1e30f, s = 0.f;
        #pragma unroll
        for (int c = 0; c < 4; c++) {
            int e2 = c * 32 + lane;
            int valid = (c < nch) && (e2 < deg);
            float l = -1e30f;
            if (valid) {
                l = l_r[c] + adi;
                l = (l >= 0.f) ? l : 0.2f * l;
            }
            l_r[c] = l;
            float mn = fmaxf(mm, l);
            s = s * __expf(mm - mn) + (valid ? __expf(l - mn) : 0.f);
            mm = mn;
        }
        #pragma unroll
        for (int o = 16; o; o >>= 1) {
            float m2 = __shfl_xor_sync(FULL, mm, o);
            float s2 = __shfl_xor_sync(FULL, s, o);
            float M = fmaxf(mm, m2);
            s = s * __expf(mm - M) + s2 * __expf(m2 - M);
            mm = M;
        }
        {
            float M = fmaxf(mm, l_self);
            s = s * __expf(mm - M) + __expf(l_self - M);
            mm = M;
        }
        m = mm;
        inv = 1.0f / s;
        #pragma unroll
        for (int c = 0; c < 4; c++) {
            if (c >= nch) break;
            int n = min(32, deg - c * 32);
            float wgt = __expf(l_r[c] - m) * inv;
            agg_window(sn_r[c], wgt, n, hw, hl, acc);
        }
    }

    // self-loop contribution (one half-warp only, to avoid double count)
    {
        float ws = __expf(l_self - m) * inv;
        uint2 raw = *reinterpret_cast<const uint2*>(&g_h[w * 32 + 2 * hl]);
        float2 va = __half22float2(*reinterpret_cast<const __half2*>(&raw.x));
        float2 vb = __half22float2(*reinterpret_cast<const __half2*>(&raw.y));
        if (hw == 0) {
            acc.x = fmaf(ws, va.x, acc.x);
            acc.y = fmaf(ws, va.y, acc.y);
            acc.z = fmaf(ws, vb.x, acc.z);
            acc.w = fmaf(ws, vb.y, acc.w);
        }
    }

    acc.x += __shfl_xor_sync(FULL, acc.x, 16);
    acc.y += __shfl_xor_sync(FULL, acc.y, 16);
    acc.z += __shfl_xor_sync(FULL, acc.z, 16);
    acc.w += __shfl_xor_sync(FULL, acc.w, 16);

    if (lane < 16) {
        float4 bv = ((const float4*)bias)[hl];
        acc.x += bv.x; acc.y += bv.y; acc.z += bv.z; acc.w += bv.w;
        acc.x = (acc.x > 0.f) ? acc.x : expm1f(acc.x);
        acc.y = (acc.y > 0.f) ? acc.y : expm1f(acc.y);
        acc.z = (acc.z > 0.f) ? acc.z : expm1f(acc.z);
        acc.w = (acc.w > 0.f) ? acc.w : expm1f(acc.w);
        ((float4*)g_out)[w * 16 + hl] = acc;
    }
}

// ---------------- global mean pool (warp per 8-node run) ---------------------
#define PNODES 8
#define NGRP   ((NN + PNODES - 1) / PNODES)
__global__ void k_pool(const void* __restrict__ batch, const void* __restrict__ ei) {
    int is32 = block_detect(ei);
    const int wid = (blockIdx.x * blockDim.x + threadIdx.x) >> 5;
    const int lane = threadIdx.x & 31;
    if (wid >= NGRP) return;
    const int i0 = wid * PNODES;

    int b = 0;
    if (lane < PNODES && i0 + lane < NN) b = ld_idx(batch, i0 + lane, is32, NG);

    int gprev = __shfl_sync(FULL, b, 0);
    float ax = 0.f, ay = 0.f, cnt = 0.f;
    #pragma unroll
    for (int k = 0; k < PNODES; k++) {
        int i = i0 + k;
        if (i >= NN) break;
        int g = __shfl_sync(FULL, b, k);
        if (g != gprev) {
            atomicAdd(&g_pool[gprev * CH + 2 * lane], ax);
            atomicAdd(&g_pool[gprev * CH + 2 * lane + 1], ay);
            if (lane == 0) atomicAdd(&g_cnt[gprev], cnt);
            ax = 0.f; ay = 0.f; cnt = 0.f; gprev = g;
        }
        float2 v = g_out[i * 32 + lane];
        ax += v.x; ay += v.y; cnt += 1.f;
    }
    atomicAdd(&g_pool[gprev * CH + 2 * lane], ax);
    atomicAdd(&g_pool[gprev * CH + 2 * lane + 1], ay);
    if (lane == 0) atomicAdd(&g_cnt[gprev], cnt);
}

// ---------------- divide + writeout + zero g_deg for next launch ------------
__global__ void k_div(float* __restrict__ dout) {
    int t = blockIdx.x * blockDim.x + threadIdx.x;
    if (t < NG * CH) dout[t] = g_pool[t] * (1.0f / fmaxf(g_cnt[t >> 6], 1.0f));
    if (t < NN) g_deg[t] = 0;    // restore for next launch
}

// ---------------- entry ------------------------------------------------------
extern "C" void kernel_launch(void* const* d_in, const int* in_sizes, int n_in,
                              void* d_out, int out_size) {
    const float* x     = (const float*)d_in[0];
    const void*  ei    = d_in[1];
    const void*  batch = d_in[2];
    const float* W1    = (const float*)d_in[3];
    const float* as1   = (const float*)d_in[4];
    const float* ad1   = (const float*)d_in[5];
    const float* b1    = (const float*)d_in[6];
    const float* W2    = (const float*)d_in[7];
    const float* as2   = (const float*)d_in[8];
    const float* ad2   = (const float*)d_in[9];
    const float* b2    = (const float*)d_in[10];
    float* dout = (float*)d_out;

    // fused: gemm1 (independent of edges) + bucket scatter (independent of x)
    k_front<<<GEMM_BLKS + SCAT_BLKS, 256>>>((const float2*)x, W1, as1, ad1, ei);

    // layer 1 aggregation
    k_agg<<<(NN * 32 + 255) / 256, 256>>>(b1);

    // layer 2
    k_gemm2<<<GEMM_BLKS, 256>>>(W2, as2, ad2);
    k_agg<<<(NN * 32 + 255) / 256, 256>>>(b2);

    // pool + divide (+ g_deg restore)
    k_pool<<<(NGRP * 32 + 255) / 256, 256>>>(batch, ei);
    k_div<<<(NN + 255) / 256, 256>>>(dout);
}